// round 9
// baseline (speedup 1.0000x reference)
#include <cuda_runtime.h>
#include <cuda_fp16.h>
#include <cstdint>

// ============================================================================
// FactoredCausalSelfAttention  (B=2, T=2048, C=1024, H=16, D=64)
// Round 9: gemm = round-7 exact (cp.async.ca).
//          attn = round-6 inner loops (low reg pressure) + launch_bounds(256,2)
//          so 2 CTAs/SM co-reside (512thr x 128regs = 64K RF, 221KB smem).
// ============================================================================

#define B_   2
#define T_   2048
#define C_   1024
#define H_   16
#define D_   64
#define BH_  (B_*H_)
#define M_GEMM (B_*T_)      // 4096
#define N_GEMM (2*C_)       // 2048
#define K_GEMM (C_)         // 1024

// ---- device scratch ----
__device__ __align__(16) __half g_Xh [(size_t)M_GEMM*K_GEMM];
__device__ __align__(16) __half g_Xl [(size_t)M_GEMM*K_GEMM];
__device__ __align__(16) __half g_Whi[(size_t)N_GEMM*K_GEMM];  // [n][k]
__device__ __align__(16) __half g_Wlo[(size_t)N_GEMM*K_GEMM];  // [n][k]
__device__ __align__(16) __half g_qh [(size_t)BH_*T_*D_];      // [bh][t][d]
__device__ __align__(16) __half g_ql [(size_t)BH_*T_*D_];
__device__ __align__(16) __half g_kh [(size_t)BH_*T_*D_];
__device__ __align__(16) __half g_kl [(size_t)BH_*T_*D_];
__device__ __align__(16) __half g_vh [(size_t)BH_*D_*T_];      // [bh][d][t]
__device__ __align__(16) __half g_vl [(size_t)BH_*D_*T_];

// ---------------------------------------------------------------- helpers ---
__device__ __forceinline__ void mma_fp16(float c[4], const uint32_t a[4],
                                         uint32_t b0, uint32_t b1)
{
    asm volatile(
        "mma.sync.aligned.m16n8k16.row.col.f32.f16.f16.f32 "
        "{%0,%1,%2,%3}, {%4,%5,%6,%7}, {%8,%9}, {%0,%1,%2,%3};\n"
        : "+f"(c[0]), "+f"(c[1]), "+f"(c[2]), "+f"(c[3])
        : "r"(a[0]), "r"(a[1]), "r"(a[2]), "r"(a[3]), "r"(b0), "r"(b1));
}

__device__ __forceinline__ void ldsm_x4(uint32_t r[4], uint32_t addr)
{
    asm volatile("ldmatrix.sync.aligned.m8n8.x4.shared.b16 {%0,%1,%2,%3}, [%4];"
                 : "=r"(r[0]), "=r"(r[1]), "=r"(r[2]), "=r"(r[3]) : "r"(addr));
}

__device__ __forceinline__ float ex2f(float x) {
    float y;
    asm("ex2.approx.f32 %0, %1;" : "=f"(y) : "f"(x));
    return y;
}

__device__ __forceinline__ void cp_async16(uint32_t smem_addr, const void* gptr) {
    asm volatile("cp.async.ca.shared.global [%0], [%1], 16;\n"
                 :: "r"(smem_addr), "l"(gptr));
}
__device__ __forceinline__ void cp_async_commit() {
    asm volatile("cp.async.commit_group;\n");
}
template<int N>
__device__ __forceinline__ void cp_async_wait() {
    asm volatile("cp.async.wait_group %0;\n" :: "n"(N));
}

// ----------------------------------------------------------------------------
// prep kernels (unchanged)
// ----------------------------------------------------------------------------
__global__ __launch_bounds__(256) void prep_x_kernel(const float* __restrict__ X)
{
    int i = blockIdx.x * 256 + threadIdx.x;
    float2 v = ((const float2*)X)[i];
    __half h0 = __float2half_rn(v.x);
    __half h1 = __float2half_rn(v.y);
    ((__half2*)g_Xh)[i] = __halves2half2(h0, h1);
    ((__half2*)g_Xl)[i] = __halves2half2(__float2half_rn(v.x - __half2float(h0)),
                                         __float2half_rn(v.y - __half2float(h1)));
}

__global__ __launch_bounds__(256) void prep_w_kernel(const float* __restrict__ W)
{
    __shared__ float t[32][33];
    const int bn = blockIdx.x, bk = blockIdx.y;
    const int tx = threadIdx.x, ty = threadIdx.y;
    #pragma unroll
    for (int j = 0; j < 4; j++)
        t[ty + 8*j][tx] = W[(size_t)(bk*32 + ty + 8*j) * N_GEMM + bn*32 + tx];
    __syncthreads();
    #pragma unroll
    for (int j = 0; j < 4; j++) {
        const int n = bn*32 + ty + 8*j;
        const int k = bk*32 + tx;
        float v = t[tx][ty + 8*j];
        __half h = __float2half_rn(v);
        g_Whi[(size_t)n * K_GEMM + k] = h;
        g_Wlo[(size_t)n * K_GEMM + k] = __float2half_rn(v - __half2float(h));
    }
}

__global__ __launch_bounds__(256) void prep_v_kernel(const float* __restrict__ xt)
{
    __shared__ float t[32][33];
    const int bh = blockIdx.z;
    const int b = bh >> 4, h = bh & 15;
    const int tt = blockIdx.x * 32;
    const int dd = blockIdx.y * 32;
    const int tx = threadIdx.x, ty = threadIdx.y;
    #pragma unroll
    for (int j = 0; j < 4; j++)
        t[ty + 8*j][tx] = xt[(size_t)(b*T_ + tt + ty + 8*j) * C_ + h*D_ + dd + tx];
    __syncthreads();
    #pragma unroll
    for (int j = 0; j < 4; j++) {
        const int d = dd + ty + 8*j;
        float v = t[tx][ty + 8*j];
        __half hh = __float2half_rn(v);
        const size_t o = ((size_t)bh*D_ + d) * T_ + tt + tx;
        g_vh[o] = hh;
        g_vl[o] = __float2half_rn(v - __half2float(hh));
    }
}

// ----------------------------------------------------------------------------
// GEMM (fp16 3-pass): qk = X @ W + bias -> split-scatter q/k hi/lo fp16
// (round-7 exact)
// ----------------------------------------------------------------------------
#define G_ARR (128*40)
#define G_STAGE (4*G_ARR)
#define GEMM_SMEM_BYTES (2*G_STAGE*2)   // 81920

__global__ __launch_bounds__(256, 2) void gemm_qk_kernel(const float* __restrict__ bias)
{
    extern __shared__ __half gsm[];
    const uint32_t smb = (uint32_t)__cvta_generic_to_shared(gsm);

    const int bx = blockIdx.x;
    const int by = blockIdx.y;
    const int tid = threadIdx.x;
    const int warp = tid >> 5;
    const int lane = tid & 31;
    const int lr = lane >> 2;
    const int lc = lane & 3;
    const int wm = warp >> 1;
    const int wn = warp & 1;

    const int aRow = (lane & 15);
    const int aCol = (lane >> 4) * 8;
    const int bRow = ((lane >> 4) << 3) + (lane & 7);
    const int bCol = ((lane >> 3) & 1) * 8;

    float c[2][8][4];
    #pragma unroll
    for (int mt = 0; mt < 2; mt++)
        #pragma unroll
        for (int nt = 0; nt < 8; nt++)
            #pragma unroll
            for (int j = 0; j < 4; j++) c[mt][nt][j] = 0.f;

    auto issue_stage = [&](int stage, int k0) {
        const uint32_t st = smb + (uint32_t)(stage * G_STAGE) * 2;
        #pragma unroll
        for (int i = 0; i < 8; i++) {
            int idx = tid + i * 256;
            int sec = idx >> 9;
            int sub = idx & 511;
            int r   = sub >> 2;
            int c8  = (sub & 3) * 8;
            const __half* src;
            if      (sec == 0) src = g_Xh  + (size_t)(by*128 + r) * K_GEMM + k0 + c8;
            else if (sec == 1) src = g_Xl  + (size_t)(by*128 + r) * K_GEMM + k0 + c8;
            else if (sec == 2) src = g_Whi + (size_t)(bx*128 + r) * K_GEMM + k0 + c8;
            else               src = g_Wlo + (size_t)(bx*128 + r) * K_GEMM + k0 + c8;
            cp_async16(st + (uint32_t)(sec * G_ARR + r * 40 + c8) * 2, src);
        }
        cp_async_commit();
    };

    issue_stage(0, 0);

    const int NIT = K_GEMM / 32;
    for (int it = 0; it < NIT; it++) {
        if (it + 1 < NIT) {
            issue_stage((it + 1) & 1, (it + 1) * 32);
            cp_async_wait<1>();
        } else {
            cp_async_wait<0>();
        }
        __syncthreads();

        const uint32_t Ah = smb + (uint32_t)((it & 1) * G_STAGE) * 2;
        const uint32_t Al = Ah + G_ARR * 2;
        const uint32_t Bh = Ah + 2 * G_ARR * 2;
        const uint32_t Bl = Ah + 3 * G_ARR * 2;

        #pragma unroll
        for (int ks = 0; ks < 2; ks++) {
            uint32_t ah[2][4], al[2][4];
            #pragma unroll
            for (int mt = 0; mt < 2; mt++) {
                const uint32_t ao =
                    (uint32_t)(((wm*32 + mt*16 + aRow) * 40) + 16*ks + aCol) * 2;
                ldsm_x4(ah[mt], Ah + ao);
                ldsm_x4(al[mt], Al + ao);
            }
            #pragma unroll
            for (int ntp = 0; ntp < 4; ntp++) {
                const uint32_t bo =
                    (uint32_t)(((wn*64 + ntp*16 + bRow) * 40) + 16*ks + bCol) * 2;
                uint32_t bh4[4], bl4[4];
                ldsm_x4(bh4, Bh + bo);
                ldsm_x4(bl4, Bl + bo);
                #pragma unroll
                for (int half = 0; half < 2; half++)
                    #pragma unroll
                    for (int mt = 0; mt < 2; mt++)
                        mma_fp16(c[mt][2*ntp+half], ah[mt], bh4[2*half], bh4[2*half+1]);
                #pragma unroll
                for (int half = 0; half < 2; half++)
                    #pragma unroll
                    for (int mt = 0; mt < 2; mt++)
                        mma_fp16(c[mt][2*ntp+half], ah[mt], bl4[2*half], bl4[2*half+1]);
                #pragma unroll
                for (int half = 0; half < 2; half++)
                    #pragma unroll
                    for (int mt = 0; mt < 2; mt++)
                        mma_fp16(c[mt][2*ntp+half], al[mt], bh4[2*half], bh4[2*half+1]);
            }
        }
        __syncthreads();
    }

    #pragma unroll
    for (int mt = 0; mt < 2; mt++) {
        #pragma unroll
        for (int rr = 0; rr < 2; rr++) {
            const int m = by*128 + wm*32 + mt*16 + rr*8 + lr;
            const int b = m >> 11;
            const int t = m & (T_ - 1);
            #pragma unroll
            for (int nt = 0; nt < 8; nt++) {
                const int n0 = bx*128 + wn*64 + nt*8 + 2*lc;
                const float v0 = c[mt][nt][rr*2 + 0] + bias[n0];
                const float v1 = c[mt][nt][rr*2 + 1] + bias[n0 + 1];
                __half h0 = __float2half_rn(v0);
                __half h1 = __float2half_rn(v1);
                __half l0 = __float2half_rn(v0 - __half2float(h0));
                __half l1 = __float2half_rn(v1 - __half2float(h1));
                if (n0 < C_) {
                    const int hh = n0 >> 6, d = n0 & 63;
                    const size_t o = (((size_t)(b*H_ + hh)) * T_ + t) * D_ + d;
                    *(__half2*)&g_qh[o] = __halves2half2(h0, h1);
                    *(__half2*)&g_ql[o] = __halves2half2(l0, l1);
                } else {
                    const int n2 = n0 - C_;
                    const int hh = n2 >> 6, d = n2 & 63;
                    const size_t o = (((size_t)(b*H_ + hh)) * T_ + t) * D_ + d;
                    *(__half2*)&g_kh[o] = __halves2half2(h0, h1);
                    *(__half2*)&g_kl[o] = __halves2half2(l0, l1);
                }
            }
        }
    }
}

// ----------------------------------------------------------------------------
// Flash attention: fp16 3-pass QK^T and PV, ldmatrix frags, cp.async KV pipe.
// Round-6 inner loops (no fragment hoisting: ~120 live regs) +
// __launch_bounds__(256,2): 2 CTAs/SM (exactly 64K RF, 221KB smem).
// ----------------------------------------------------------------------------
#define A_STAGE 36864
#define A_PQ    73728
#define ATTN_SMEM_BYTES 110592

__global__ __launch_bounds__(256, 2) void attn_kernel(float* __restrict__ out)
{
    extern __shared__ char smraw[];
    const uint32_t sm_base = (uint32_t)__cvta_generic_to_shared(smraw);
    __half* Ph  = (__half*)(smraw + A_PQ);
    __half* Pl  = Ph + 128*72;
    const uint32_t PhU = sm_base + A_PQ;
    const uint32_t PlU = PhU + 128*72*2;

    const int bh = blockIdx.y;
    const int b  = bh >> 4;
    const int h  = bh & 15;
    const int tid  = threadIdx.x;
    const int warp = tid >> 5;
    const int lane = tid & 31;
    const int lr = lane >> 2;
    const int lc = lane & 3;
    const int qt = gridDim.x - 1 - blockIdx.x;
    const int t0 = qt * 128;

    const int aRow = (lane & 15);
    const int aCol = (lane >> 4) * 8;
    const int bRow = ((lane >> 4) << 3) + (lane & 7);
    const int bCol = ((lane >> 3) & 1) * 8;

    {
        __half* Qhs = Ph;
        __half* Qls = Pl;
        #pragma unroll
        for (int i = 0; i < 4; i++) {
            int idx = tid + i * 256;
            int r = idx >> 3, c8 = (idx & 7) * 8;
            *(float4*)&Qhs[r*72 + c8] =
                *(const float4*)(g_qh + ((size_t)bh*T_ + t0 + r)*D_ + c8);
            *(float4*)&Qls[r*72 + c8] =
                *(const float4*)(g_ql + ((size_t)bh*T_ + t0 + r)*D_ + c8);
        }
    }
    __syncthreads();

    uint32_t qfh[4][4], qfl[4][4];
    #pragma unroll
    for (int ks = 0; ks < 4; ks++) {
        const uint32_t qo = (uint32_t)(((warp*16 + aRow) * 72) + 16*ks + aCol) * 2;
        ldsm_x4(qfh[ks], PhU + qo);
        ldsm_x4(qfl[ks], PlU + qo);
    }
    __syncthreads();

    float o[8][4];
    #pragma unroll
    for (int dt = 0; dt < 8; dt++)
        #pragma unroll
        for (int j = 0; j < 4; j++) o[dt][j] = 0.f;

    float m0 = -1e30f, m1 = -1e30f;
    float l0 = 0.f, l1 = 0.f;
    const float C2 = 0.125f * 1.44269504089f;

    const int rg0 = t0 + warp*16 + lr;
    const int rg1 = rg0 + 8;
    const int prow0 = (warp*16 + lr) * 72;
    const int prow1 = prow0 + 8*72;

    auto issue_tile = [&](int stage, int j0) {
        const uint32_t st = sm_base + (uint32_t)stage * A_STAGE;
        #pragma unroll
        for (int i = 0; i < 8; i++) {
            int idx = tid + i * 256;
            int sec = idx >> 9;
            int sub = idx & 511;
            int r   = sub >> 3;
            int c8  = (sub & 7) * 8;
            const __half* src;
            if      (sec == 0) src = g_kh + ((size_t)bh*T_ + j0 + r)*D_ + c8;
            else if (sec == 1) src = g_kl + ((size_t)bh*T_ + j0 + r)*D_ + c8;
            else if (sec == 2) src = g_vh + ((size_t)bh*D_ + r)*T_ + j0 + c8;
            else               src = g_vl + ((size_t)bh*D_ + r)*T_ + j0 + c8;
            cp_async16(st + (uint32_t)(sec * 9216) + (uint32_t)(r*72 + c8)*2, src);
        }
        cp_async_commit();
    };

    const int ntiles = 2*qt + 2;
    issue_tile(0, 0);

    for (int it = 0; it < ntiles; it++) {
        const int j0 = it * 64;
        if (it + 1 < ntiles) {
            issue_tile((it + 1) & 1, (it + 1) * 64);
            cp_async_wait<1>();
        } else {
            cp_async_wait<0>();
        }
        __syncthreads();

        const uint32_t KhiU = sm_base + (uint32_t)((it & 1) * A_STAGE);
        const uint32_t KloU = KhiU + 9216;
        const uint32_t VhU  = KhiU + 2*9216;
        const uint32_t VlU  = KhiU + 3*9216;

        // ---- S = Q K^T  (fp16 3-pass, per-ntp fragments: low reg pressure) ----
        float s[8][4];
        #pragma unroll
        for (int nt = 0; nt < 8; nt++)
            #pragma unroll
            for (int j = 0; j < 4; j++) s[nt][j] = 0.f;

        #pragma unroll
        for (int ks = 0; ks < 4; ks++) {
            #pragma unroll
            for (int ntp = 0; ntp < 4; ntp++) {
                const uint32_t ko =
                    (uint32_t)(((ntp*16 + bRow) * 72) + 16*ks + bCol) * 2;
                uint32_t kh4[4], kl4[4];
                ldsm_x4(kh4, KhiU + ko);
                ldsm_x4(kl4, KloU + ko);
                #pragma unroll
                for (int half = 0; half < 2; half++) {
                    const int nt = 2*ntp + half;
                    mma_fp16(s[nt], qfh[ks], kh4[2*half], kh4[2*half+1]);
                    mma_fp16(s[nt], qfh[ks], kl4[2*half], kl4[2*half+1]);
                    mma_fp16(s[nt], qfl[ks], kh4[2*half], kh4[2*half+1]);
                }
            }
        }

        // ---- causal mask ----
        if (j0 + 63 > t0) {
            #pragma unroll
            for (int nt = 0; nt < 8; nt++) {
                int cg = j0 + nt*8 + 2*lc;
                if (cg     > rg0) s[nt][0] = -1e30f;
                if (cg + 1 > rg0) s[nt][1] = -1e30f;
                if (cg     > rg1) s[nt][2] = -1e30f;
                if (cg + 1 > rg1) s[nt][3] = -1e30f;
            }
        }

        // ---- online softmax ----
        float t0m = -1e30f, t1m = -1e30f;
        #pragma unroll
        for (int nt = 0; nt < 8; nt++) {
            t0m = fmaxf(t0m, fmaxf(s[nt][0], s[nt][1]));
            t1m = fmaxf(t1m, fmaxf(s[nt][2], s[nt][3]));
        }
        t0m = fmaxf(t0m, __shfl_xor_sync(0xffffffffu, t0m, 1));
        t0m = fmaxf(t0m, __shfl_xor_sync(0xffffffffu, t0m, 2));
        t1m = fmaxf(t1m, __shfl_xor_sync(0xffffffffu, t1m, 1));
        t1m = fmaxf(t1m, __shfl_xor_sync(0xffffffffu, t1m, 2));

        const float mn0 = fmaxf(m0, t0m);
        const float mn1 = fmaxf(m1, t1m);
        const float a0 = ex2f((m0 - mn0) * C2);
        const float a1 = ex2f((m1 - mn1) * C2);
        m0 = mn0; m1 = mn1;
        l0 *= a0; l1 *= a1;
        #pragma unroll
        for (int dt = 0; dt < 8; dt++) {
            o[dt][0] *= a0; o[dt][1] *= a0;
            o[dt][2] *= a1; o[dt][3] *= a1;
        }

        // ---- p split into fp16 hi/lo; l in fp32 ----
        #pragma unroll
        for (int nt = 0; nt < 8; nt++) {
            float p0 = ex2f((s[nt][0] - m0) * C2);
            float p1 = ex2f((s[nt][1] - m0) * C2);
            float p2 = ex2f((s[nt][2] - m1) * C2);
            float p3 = ex2f((s[nt][3] - m1) * C2);
            l0 += p0 + p1;
            l1 += p2 + p3;
            __half h0 = __float2half_rn(p0), h1 = __float2half_rn(p1);
            __half h2 = __float2half_rn(p2), h3 = __float2half_rn(p3);
            *(__half2*)&Ph[prow0 + nt*8 + 2*lc] = __halves2half2(h0, h1);
            *(__half2*)&Ph[prow1 + nt*8 + 2*lc] = __halves2half2(h2, h3);
            *(__half2*)&Pl[prow0 + nt*8 + 2*lc] =
                __halves2half2(__float2half_rn(p0 - __half2float(h0)),
                               __float2half_rn(p1 - __half2float(h1)));
            *(__half2*)&Pl[prow1 + nt*8 + 2*lc] =
                __halves2half2(__float2half_rn(p2 - __half2float(h2)),
                               __float2half_rn(p3 - __half2float(h3)));
        }
        __syncwarp();   // P rows are per-warp private

        // ---- O += P V  (fp16 3-pass, per-dtp fragments) ----
        #pragma unroll
        for (int ks = 0; ks < 4; ks++) {
            uint32_t pah[4], pal[4];
            const uint32_t po =
                (uint32_t)(((warp*16 + aRow) * 72) + 16*ks + aCol) * 2;
            ldsm_x4(pah, PhU + po);
            ldsm_x4(pal, PlU + po);
            #pragma unroll
            for (int dtp = 0; dtp < 4; dtp++) {
                const uint32_t vo =
                    (uint32_t)(((dtp*16 + bRow) * 72) + 16*ks + bCol) * 2;
                uint32_t vh4[4], vl4[4];
                ldsm_x4(vh4, VhU + vo);
                ldsm_x4(vl4, VlU + vo);
                #pragma unroll
                for (int half = 0; half < 2; half++) {
                    const int dt = 2*dtp + half;
                    mma_fp16(o[dt], pah, vh4[2*half], vh4[2*half+1]);
                    mma_fp16(o[dt], pah, vl4[2*half], vl4[2*half+1]);
                    mma_fp16(o[dt], pal, vh4[2*half], vh4[2*half+1]);
                }
            }
        }
        __syncthreads();
    }

    // ---- finalize ----
    l0 += __shfl_xor_sync(0xffffffffu, l0, 1);
    l0 += __shfl_xor_sync(0xffffffffu, l0, 2);
    l1 += __shfl_xor_sync(0xffffffffu, l1, 1);
    l1 += __shfl_xor_sync(0xffffffffu, l1, 2);
    const float inv0 = 1.f / l0;
    const float inv1 = 1.f / l1;

    float* out0 = out + ((size_t)(b*T_ + rg0))*C_ + h*D_;
    float* out1 = out + ((size_t)(b*T_ + rg1))*C_ + h*D_;
    #pragma unroll
    for (int dt = 0; dt < 8; dt++) {
        *(float2*)(out0 + dt*8 + 2*lc) = make_float2(o[dt][0]*inv0, o[dt][1]*inv0);
        *(float2*)(out1 + dt*8 + 2*lc) = make_float2(o[dt][2]*inv1, o[dt][3]*inv1);
    }
}

// ----------------------------------------------------------------------------
extern "C" void kernel_launch(void* const* d_in, const int* in_sizes, int n_in,
                              void* d_out, int out_size)
{
    const float* x_norm = (const float*)d_in[0];
    const float* xt_cur = (const float*)d_in[1];
    const float* W_attn = (const float*)d_in[2];
    const float* b_attn = (const float*)d_in[3];
    float* out = (float*)d_out;

    cudaFuncSetAttribute(gemm_qk_kernel,
                         cudaFuncAttributeMaxDynamicSharedMemorySize, GEMM_SMEM_BYTES);
    cudaFuncSetAttribute(attn_kernel,
                         cudaFuncAttributeMaxDynamicSharedMemorySize, ATTN_SMEM_BYTES);

    prep_x_kernel<<<(M_GEMM*K_GEMM/2)/256, 256>>>(x_norm);
    prep_w_kernel<<<dim3(N_GEMM/32, K_GEMM/32), dim3(32, 8)>>>(W_attn);
    prep_v_kernel<<<dim3(T_/32, D_/32, BH_), dim3(32, 8)>>>(xt_cur);

    dim3 g1(N_GEMM/128, M_GEMM/128);   // (16, 32)
    gemm_qk_kernel<<<g1, 256, GEMM_SMEM_BYTES>>>(b_attn);

    dim3 g2(T_/128, B_*H_);            // (16, 32)
    attn_kernel<<<g2, 256, ATTN_SMEM_BYTES>>>(out);
}

// round 10
// speedup vs baseline: 1.0949x; 1.0949x over previous
#include <cuda_runtime.h>
#include <cuda_fp16.h>
#include <cstdint>

// ============================================================================
// FactoredCausalSelfAttention  (B=2, T=2048, C=1024, H=16, D=64)
// Round 10: gemm = round-7 exact.
//           attn = 128-thread CTAs over 64 q-rows (4 warps), smem 92KB ->
//           2 CTAs/SM via smem/regs naturally (no register cap, no spills).
// ============================================================================

#define B_   2
#define T_   2048
#define C_   1024
#define H_   16
#define D_   64
#define BH_  (B_*H_)
#define M_GEMM (B_*T_)      // 4096
#define N_GEMM (2*C_)       // 2048
#define K_GEMM (C_)         // 1024

// ---- device scratch ----
__device__ __align__(16) __half g_Xh [(size_t)M_GEMM*K_GEMM];
__device__ __align__(16) __half g_Xl [(size_t)M_GEMM*K_GEMM];
__device__ __align__(16) __half g_Whi[(size_t)N_GEMM*K_GEMM];  // [n][k]
__device__ __align__(16) __half g_Wlo[(size_t)N_GEMM*K_GEMM];  // [n][k]
__device__ __align__(16) __half g_qh [(size_t)BH_*T_*D_];      // [bh][t][d]
__device__ __align__(16) __half g_ql [(size_t)BH_*T_*D_];
__device__ __align__(16) __half g_kh [(size_t)BH_*T_*D_];
__device__ __align__(16) __half g_kl [(size_t)BH_*T_*D_];
__device__ __align__(16) __half g_vh [(size_t)BH_*D_*T_];      // [bh][d][t]
__device__ __align__(16) __half g_vl [(size_t)BH_*D_*T_];

// ---------------------------------------------------------------- helpers ---
__device__ __forceinline__ void mma_fp16(float c[4], const uint32_t a[4],
                                         uint32_t b0, uint32_t b1)
{
    asm volatile(
        "mma.sync.aligned.m16n8k16.row.col.f32.f16.f16.f32 "
        "{%0,%1,%2,%3}, {%4,%5,%6,%7}, {%8,%9}, {%0,%1,%2,%3};\n"
        : "+f"(c[0]), "+f"(c[1]), "+f"(c[2]), "+f"(c[3])
        : "r"(a[0]), "r"(a[1]), "r"(a[2]), "r"(a[3]), "r"(b0), "r"(b1));
}

__device__ __forceinline__ void ldsm_x4(uint32_t r[4], uint32_t addr)
{
    asm volatile("ldmatrix.sync.aligned.m8n8.x4.shared.b16 {%0,%1,%2,%3}, [%4];"
                 : "=r"(r[0]), "=r"(r[1]), "=r"(r[2]), "=r"(r[3]) : "r"(addr));
}

__device__ __forceinline__ float ex2f(float x) {
    float y;
    asm("ex2.approx.f32 %0, %1;" : "=f"(y) : "f"(x));
    return y;
}

__device__ __forceinline__ void cp_async16(uint32_t smem_addr, const void* gptr) {
    asm volatile("cp.async.ca.shared.global [%0], [%1], 16;\n"
                 :: "r"(smem_addr), "l"(gptr));
}
__device__ __forceinline__ void cp_async_commit() {
    asm volatile("cp.async.commit_group;\n");
}
template<int N>
__device__ __forceinline__ void cp_async_wait() {
    asm volatile("cp.async.wait_group %0;\n" :: "n"(N));
}

// ----------------------------------------------------------------------------
// prep kernels (unchanged)
// ----------------------------------------------------------------------------
__global__ __launch_bounds__(256) void prep_x_kernel(const float* __restrict__ X)
{
    int i = blockIdx.x * 256 + threadIdx.x;
    float2 v = ((const float2*)X)[i];
    __half h0 = __float2half_rn(v.x);
    __half h1 = __float2half_rn(v.y);
    ((__half2*)g_Xh)[i] = __halves2half2(h0, h1);
    ((__half2*)g_Xl)[i] = __halves2half2(__float2half_rn(v.x - __half2float(h0)),
                                         __float2half_rn(v.y - __half2float(h1)));
}

__global__ __launch_bounds__(256) void prep_w_kernel(const float* __restrict__ W)
{
    __shared__ float t[32][33];
    const int bn = blockIdx.x, bk = blockIdx.y;
    const int tx = threadIdx.x, ty = threadIdx.y;
    #pragma unroll
    for (int j = 0; j < 4; j++)
        t[ty + 8*j][tx] = W[(size_t)(bk*32 + ty + 8*j) * N_GEMM + bn*32 + tx];
    __syncthreads();
    #pragma unroll
    for (int j = 0; j < 4; j++) {
        const int n = bn*32 + ty + 8*j;
        const int k = bk*32 + tx;
        float v = t[tx][ty + 8*j];
        __half h = __float2half_rn(v);
        g_Whi[(size_t)n * K_GEMM + k] = h;
        g_Wlo[(size_t)n * K_GEMM + k] = __float2half_rn(v - __half2float(h));
    }
}

__global__ __launch_bounds__(256) void prep_v_kernel(const float* __restrict__ xt)
{
    __shared__ float t[32][33];
    const int bh = blockIdx.z;
    const int b = bh >> 4, h = bh & 15;
    const int tt = blockIdx.x * 32;
    const int dd = blockIdx.y * 32;
    const int tx = threadIdx.x, ty = threadIdx.y;
    #pragma unroll
    for (int j = 0; j < 4; j++)
        t[ty + 8*j][tx] = xt[(size_t)(b*T_ + tt + ty + 8*j) * C_ + h*D_ + dd + tx];
    __syncthreads();
    #pragma unroll
    for (int j = 0; j < 4; j++) {
        const int d = dd + ty + 8*j;
        float v = t[tx][ty + 8*j];
        __half hh = __float2half_rn(v);
        const size_t o = ((size_t)bh*D_ + d) * T_ + tt + tx;
        g_vh[o] = hh;
        g_vl[o] = __float2half_rn(v - __half2float(hh));
    }
}

// ----------------------------------------------------------------------------
// GEMM (fp16 3-pass): qk = X @ W + bias -> split-scatter q/k hi/lo fp16
// (round-7 exact)
// ----------------------------------------------------------------------------
#define G_ARR (128*40)
#define G_STAGE (4*G_ARR)
#define GEMM_SMEM_BYTES (2*G_STAGE*2)   // 81920

__global__ __launch_bounds__(256, 2) void gemm_qk_kernel(const float* __restrict__ bias)
{
    extern __shared__ __half gsm[];
    const uint32_t smb = (uint32_t)__cvta_generic_to_shared(gsm);

    const int bx = blockIdx.x;
    const int by = blockIdx.y;
    const int tid = threadIdx.x;
    const int warp = tid >> 5;
    const int lane = tid & 31;
    const int lr = lane >> 2;
    const int lc = lane & 3;
    const int wm = warp >> 1;
    const int wn = warp & 1;

    const int aRow = (lane & 15);
    const int aCol = (lane >> 4) * 8;
    const int bRow = ((lane >> 4) << 3) + (lane & 7);
    const int bCol = ((lane >> 3) & 1) * 8;

    float c[2][8][4];
    #pragma unroll
    for (int mt = 0; mt < 2; mt++)
        #pragma unroll
        for (int nt = 0; nt < 8; nt++)
            #pragma unroll
            for (int j = 0; j < 4; j++) c[mt][nt][j] = 0.f;

    auto issue_stage = [&](int stage, int k0) {
        const uint32_t st = smb + (uint32_t)(stage * G_STAGE) * 2;
        #pragma unroll
        for (int i = 0; i < 8; i++) {
            int idx = tid + i * 256;
            int sec = idx >> 9;
            int sub = idx & 511;
            int r   = sub >> 2;
            int c8  = (sub & 3) * 8;
            const __half* src;
            if      (sec == 0) src = g_Xh  + (size_t)(by*128 + r) * K_GEMM + k0 + c8;
            else if (sec == 1) src = g_Xl  + (size_t)(by*128 + r) * K_GEMM + k0 + c8;
            else if (sec == 2) src = g_Whi + (size_t)(bx*128 + r) * K_GEMM + k0 + c8;
            else               src = g_Wlo + (size_t)(bx*128 + r) * K_GEMM + k0 + c8;
            cp_async16(st + (uint32_t)(sec * G_ARR + r * 40 + c8) * 2, src);
        }
        cp_async_commit();
    };

    issue_stage(0, 0);

    const int NIT = K_GEMM / 32;
    for (int it = 0; it < NIT; it++) {
        if (it + 1 < NIT) {
            issue_stage((it + 1) & 1, (it + 1) * 32);
            cp_async_wait<1>();
        } else {
            cp_async_wait<0>();
        }
        __syncthreads();

        const uint32_t Ah = smb + (uint32_t)((it & 1) * G_STAGE) * 2;
        const uint32_t Al = Ah + G_ARR * 2;
        const uint32_t Bh = Ah + 2 * G_ARR * 2;
        const uint32_t Bl = Ah + 3 * G_ARR * 2;

        #pragma unroll
        for (int ks = 0; ks < 2; ks++) {
            uint32_t ah[2][4], al[2][4];
            #pragma unroll
            for (int mt = 0; mt < 2; mt++) {
                const uint32_t ao =
                    (uint32_t)(((wm*32 + mt*16 + aRow) * 40) + 16*ks + aCol) * 2;
                ldsm_x4(ah[mt], Ah + ao);
                ldsm_x4(al[mt], Al + ao);
            }
            #pragma unroll
            for (int ntp = 0; ntp < 4; ntp++) {
                const uint32_t bo =
                    (uint32_t)(((wn*64 + ntp*16 + bRow) * 40) + 16*ks + bCol) * 2;
                uint32_t bh4[4], bl4[4];
                ldsm_x4(bh4, Bh + bo);
                ldsm_x4(bl4, Bl + bo);
                #pragma unroll
                for (int half = 0; half < 2; half++)
                    #pragma unroll
                    for (int mt = 0; mt < 2; mt++)
                        mma_fp16(c[mt][2*ntp+half], ah[mt], bh4[2*half], bh4[2*half+1]);
                #pragma unroll
                for (int half = 0; half < 2; half++)
                    #pragma unroll
                    for (int mt = 0; mt < 2; mt++)
                        mma_fp16(c[mt][2*ntp+half], ah[mt], bl4[2*half], bl4[2*half+1]);
                #pragma unroll
                for (int half = 0; half < 2; half++)
                    #pragma unroll
                    for (int mt = 0; mt < 2; mt++)
                        mma_fp16(c[mt][2*ntp+half], al[mt], bh4[2*half], bh4[2*half+1]);
            }
        }
        __syncthreads();
    }

    #pragma unroll
    for (int mt = 0; mt < 2; mt++) {
        #pragma unroll
        for (int rr = 0; rr < 2; rr++) {
            const int m = by*128 + wm*32 + mt*16 + rr*8 + lr;
            const int b = m >> 11;
            const int t = m & (T_ - 1);
            #pragma unroll
            for (int nt = 0; nt < 8; nt++) {
                const int n0 = bx*128 + wn*64 + nt*8 + 2*lc;
                const float v0 = c[mt][nt][rr*2 + 0] + bias[n0];
                const float v1 = c[mt][nt][rr*2 + 1] + bias[n0 + 1];
                __half h0 = __float2half_rn(v0);
                __half h1 = __float2half_rn(v1);
                __half l0 = __float2half_rn(v0 - __half2float(h0));
                __half l1 = __float2half_rn(v1 - __half2float(h1));
                if (n0 < C_) {
                    const int hh = n0 >> 6, d = n0 & 63;
                    const size_t o = (((size_t)(b*H_ + hh)) * T_ + t) * D_ + d;
                    *(__half2*)&g_qh[o] = __halves2half2(h0, h1);
                    *(__half2*)&g_ql[o] = __halves2half2(l0, l1);
                } else {
                    const int n2 = n0 - C_;
                    const int hh = n2 >> 6, d = n2 & 63;
                    const size_t o = (((size_t)(b*H_ + hh)) * T_ + t) * D_ + d;
                    *(__half2*)&g_kh[o] = __halves2half2(h0, h1);
                    *(__half2*)&g_kl[o] = __halves2half2(l0, l1);
                }
            }
        }
    }
}

// ----------------------------------------------------------------------------
// Flash attention: 128 threads (4 warps) per CTA, 64 q-rows per CTA.
// fp16 3-pass QK^T and PV, ldmatrix frags, cp.async double-buffered KV.
// smem: stage s @ s*36864: Khi[64][72] Klo Vh Vl (half, 9216B each)
//       P/Q @ 73728: Ph[64][72] (9216B), Pl @ +9216   -> total 92160B
// 2 CTAs/SM (184KB smem, ~40K regs) without register caps.
// ----------------------------------------------------------------------------
#define A_STAGE 36864
#define A_PQ    73728
#define ATTN_SMEM_BYTES 92160
#define A_THREADS 128

__global__ __launch_bounds__(A_THREADS) void attn_kernel(float* __restrict__ out)
{
    extern __shared__ char smraw[];
    const uint32_t sm_base = (uint32_t)__cvta_generic_to_shared(smraw);
    __half* Ph  = (__half*)(smraw + A_PQ);
    __half* Pl  = Ph + 64*72;
    const uint32_t PhU = sm_base + A_PQ;
    const uint32_t PlU = PhU + 64*72*2;

    const int bh = blockIdx.y;
    const int b  = bh >> 4;
    const int h  = bh & 15;
    const int tid  = threadIdx.x;
    const int warp = tid >> 5;          // 0..3
    const int lane = tid & 31;
    const int lr = lane >> 2;
    const int lc = lane & 3;
    const int qt = gridDim.x - 1 - blockIdx.x;   // heavy tiles first
    const int t0 = qt * 64;

    const int aRow = (lane & 15);
    const int aCol = (lane >> 4) * 8;
    const int bRow = ((lane >> 4) << 3) + (lane & 7);
    const int bCol = ((lane >> 3) & 1) * 8;

    // ---- stage Q hi/lo (64 rows) into P region ----
    {
        __half* Qhs = Ph;
        __half* Qls = Pl;
        #pragma unroll
        for (int i = 0; i < 4; i++) {
            int idx = tid + i * A_THREADS;      // 0..511 float4s
            int r = idx >> 3, c8 = (idx & 7) * 8;
            *(float4*)&Qhs[r*72 + c8] =
                *(const float4*)(g_qh + ((size_t)bh*T_ + t0 + r)*D_ + c8);
            *(float4*)&Qls[r*72 + c8] =
                *(const float4*)(g_ql + ((size_t)bh*T_ + t0 + r)*D_ + c8);
        }
    }
    __syncthreads();

    uint32_t qfh[4][4], qfl[4][4];
    #pragma unroll
    for (int ks = 0; ks < 4; ks++) {
        const uint32_t qo = (uint32_t)(((warp*16 + aRow) * 72) + 16*ks + aCol) * 2;
        ldsm_x4(qfh[ks], PhU + qo);
        ldsm_x4(qfl[ks], PlU + qo);
    }
    __syncthreads();

    float o[8][4];
    #pragma unroll
    for (int dt = 0; dt < 8; dt++)
        #pragma unroll
        for (int j = 0; j < 4; j++) o[dt][j] = 0.f;

    float m0 = -1e30f, m1 = -1e30f;
    float l0 = 0.f, l1 = 0.f;
    const float C2 = 0.125f * 1.44269504089f;

    const int rg0 = t0 + warp*16 + lr;
    const int rg1 = rg0 + 8;
    const int prow0 = (warp*16 + lr) * 72;
    const int prow1 = prow0 + 8*72;

    // ---- KV tile loader: Khi,Klo [kv][d]; Vh,Vl [d][kv] ----
    auto issue_tile = [&](int stage, int j0) {
        const uint32_t st = sm_base + (uint32_t)stage * A_STAGE;
        #pragma unroll
        for (int i = 0; i < 16; i++) {
            int idx = tid + i * A_THREADS;   // 0..2047 16B chunks
            int sec = idx >> 9;              // 0:Khi 1:Klo 2:Vh 3:Vl
            int sub = idx & 511;
            int r   = sub >> 3;              // 0..63
            int c8  = (sub & 7) * 8;
            const __half* src;
            if      (sec == 0) src = g_kh + ((size_t)bh*T_ + j0 + r)*D_ + c8;
            else if (sec == 1) src = g_kl + ((size_t)bh*T_ + j0 + r)*D_ + c8;
            else if (sec == 2) src = g_vh + ((size_t)bh*D_ + r)*T_ + j0 + c8;
            else               src = g_vl + ((size_t)bh*D_ + r)*T_ + j0 + c8;
            cp_async16(st + (uint32_t)(sec * 9216) + (uint32_t)(r*72 + c8)*2, src);
        }
        cp_async_commit();
    };

    const int ntiles = qt + 1;
    issue_tile(0, 0);

    for (int it = 0; it < ntiles; it++) {
        const int j0 = it * 64;
        if (it + 1 < ntiles) {
            issue_tile((it + 1) & 1, (it + 1) * 64);
            cp_async_wait<1>();
        } else {
            cp_async_wait<0>();
        }
        __syncthreads();

        const uint32_t KhiU = sm_base + (uint32_t)((it & 1) * A_STAGE);
        const uint32_t KloU = KhiU + 9216;
        const uint32_t VhU  = KhiU + 2*9216;
        const uint32_t VlU  = KhiU + 3*9216;

        // ---- S = Q K^T  (fp16 3-pass) ----
        float s[8][4];
        #pragma unroll
        for (int nt = 0; nt < 8; nt++)
            #pragma unroll
            for (int j = 0; j < 4; j++) s[nt][j] = 0.f;

        #pragma unroll
        for (int ks = 0; ks < 4; ks++) {
            #pragma unroll
            for (int ntp = 0; ntp < 4; ntp++) {
                const uint32_t ko =
                    (uint32_t)(((ntp*16 + bRow) * 72) + 16*ks + bCol) * 2;
                uint32_t kh4[4], kl4[4];
                ldsm_x4(kh4, KhiU + ko);
                ldsm_x4(kl4, KloU + ko);
                #pragma unroll
                for (int half = 0; half < 2; half++) {
                    const int nt = 2*ntp + half;
                    mma_fp16(s[nt], qfh[ks], kh4[2*half], kh4[2*half+1]);
                    mma_fp16(s[nt], qfh[ks], kl4[2*half], kl4[2*half+1]);
                    mma_fp16(s[nt], qfl[ks], kh4[2*half], kh4[2*half+1]);
                }
            }
        }

        // ---- causal mask (only the last tile straddles the diagonal) ----
        if (j0 + 63 > t0) {
            #pragma unroll
            for (int nt = 0; nt < 8; nt++) {
                int cg = j0 + nt*8 + 2*lc;
                if (cg     > rg0) s[nt][0] = -1e30f;
                if (cg + 1 > rg0) s[nt][1] = -1e30f;
                if (cg     > rg1) s[nt][2] = -1e30f;
                if (cg + 1 > rg1) s[nt][3] = -1e30f;
            }
        }

        // ---- online softmax ----
        float t0m = -1e30f, t1m = -1e30f;
        #pragma unroll
        for (int nt = 0; nt < 8; nt++) {
            t0m = fmaxf(t0m, fmaxf(s[nt][0], s[nt][1]));
            t1m = fmaxf(t1m, fmaxf(s[nt][2], s[nt][3]));
        }
        t0m = fmaxf(t0m, __shfl_xor_sync(0xffffffffu, t0m, 1));
        t0m = fmaxf(t0m, __shfl_xor_sync(0xffffffffu, t0m, 2));
        t1m = fmaxf(t1m, __shfl_xor_sync(0xffffffffu, t1m, 1));
        t1m = fmaxf(t1m, __shfl_xor_sync(0xffffffffu, t1m, 2));

        const float mn0 = fmaxf(m0, t0m);
        const float mn1 = fmaxf(m1, t1m);
        const float a0 = ex2f((m0 - mn0) * C2);
        const float a1 = ex2f((m1 - mn1) * C2);
        m0 = mn0; m1 = mn1;
        l0 *= a0; l1 *= a1;
        #pragma unroll
        for (int dt = 0; dt < 8; dt++) {
            o[dt][0] *= a0; o[dt][1] *= a0;
            o[dt][2] *= a1; o[dt][3] *= a1;
        }

        // ---- p split into fp16 hi/lo; l in fp32 ----
        #pragma unroll
        for (int nt = 0; nt < 8; nt++) {
            float p0 = ex2f((s[nt][0] - m0) * C2);
            float p1 = ex2f((s[nt][1] - m0) * C2);
            float p2 = ex2f((s[nt][2] - m1) * C2);
            float p3 = ex2f((s[nt][3] - m1) * C2);
            l0 += p0 + p1;
            l1 += p2 + p3;
            __half h0 = __float2half_rn(p0), h1 = __float2half_rn(p1);
            __half h2 = __float2half_rn(p2), h3 = __float2half_rn(p3);
            *(__half2*)&Ph[prow0 + nt*8 + 2*lc] = __halves2half2(h0, h1);
            *(__half2*)&Ph[prow1 + nt*8 + 2*lc] = __halves2half2(h2, h3);
            *(__half2*)&Pl[prow0 + nt*8 + 2*lc] =
                __halves2half2(__float2half_rn(p0 - __half2float(h0)),
                               __float2half_rn(p1 - __half2float(h1)));
            *(__half2*)&Pl[prow1 + nt*8 + 2*lc] =
                __halves2half2(__float2half_rn(p2 - __half2float(h2)),
                               __float2half_rn(p3 - __half2float(h3)));
        }
        __syncwarp();   // P rows are per-warp private

        // ---- O += P V  (fp16 3-pass) ----
        #pragma unroll
        for (int ks = 0; ks < 4; ks++) {
            uint32_t pah[4], pal[4];
            const uint32_t po =
                (uint32_t)(((warp*16 + aRow) * 72) + 16*ks + aCol) * 2;
            ldsm_x4(pah, PhU + po);
            ldsm_x4(pal, PlU + po);
            #pragma unroll
            for (int dtp = 0; dtp < 4; dtp++) {
                const uint32_t vo =
                    (uint32_t)(((dtp*16 + bRow) * 72) + 16*ks + bCol) * 2;
                uint32_t vh4[4], vl4[4];
                ldsm_x4(vh4, VhU + vo);
                ldsm_x4(vl4, VlU + vo);
                #pragma unroll
                for (int half = 0; half < 2; half++) {
                    const int dt = 2*dtp + half;
                    mma_fp16(o[dt], pah, vh4[2*half], vh4[2*half+1]);
                    mma_fp16(o[dt], pah, vl4[2*half], vl4[2*half+1]);
                    mma_fp16(o[dt], pal, vh4[2*half], vh4[2*half+1]);
                }
            }
        }
        __syncthreads();
    }

    // ---- finalize ----
    l0 += __shfl_xor_sync(0xffffffffu, l0, 1);
    l0 += __shfl_xor_sync(0xffffffffu, l0, 2);
    l1 += __shfl_xor_sync(0xffffffffu, l1, 1);
    l1 += __shfl_xor_sync(0xffffffffu, l1, 2);
    const float inv0 = 1.f / l0;
    const float inv1 = 1.f / l1;

    float* out0 = out + ((size_t)(b*T_ + rg0))*C_ + h*D_;
    float* out1 = out + ((size_t)(b*T_ + rg1))*C_ + h*D_;
    #pragma unroll
    for (int dt = 0; dt < 8; dt++) {
        *(float2*)(out0 + dt*8 + 2*lc) = make_float2(o[dt][0]*inv0, o[dt][1]*inv0);
        *(float2*)(out1 + dt*8 + 2*lc) = make_float2(o[dt][2]*inv1, o[dt][3]*inv1);
    }
}

// ----------------------------------------------------------------------------
extern "C" void kernel_launch(void* const* d_in, const int* in_sizes, int n_in,
                              void* d_out, int out_size)
{
    const float* x_norm = (const float*)d_in[0];
    const float* xt_cur = (const float*)d_in[1];
    const float* W_attn = (const float*)d_in[2];
    const float* b_attn = (const float*)d_in[3];
    float* out = (float*)d_out;

    cudaFuncSetAttribute(gemm_qk_kernel,
                         cudaFuncAttributeMaxDynamicSharedMemorySize, GEMM_SMEM_BYTES);
    cudaFuncSetAttribute(attn_kernel,
                         cudaFuncAttributeMaxDynamicSharedMemorySize, ATTN_SMEM_BYTES);

    prep_x_kernel<<<(M_GEMM*K_GEMM/2)/256, 256>>>(x_norm);
    prep_w_kernel<<<dim3(N_GEMM/32, K_GEMM/32), dim3(32, 8)>>>(W_attn);
    prep_v_kernel<<<dim3(T_/32, D_/32, BH_), dim3(32, 8)>>>(xt_cur);

    dim3 g1(N_GEMM/128, M_GEMM/128);   // (16, 32)
    gemm_qk_kernel<<<g1, 256, GEMM_SMEM_BYTES>>>(b_attn);

    dim3 g2(T_/64, B_*H_);             // (32, 32)
    attn_kernel<<<g2, A_THREADS, ATTN_SMEM_BYTES>>>(out);
}